// round 17
// baseline (speedup 1.0000x reference)
#include <cuda_runtime.h>
#include <cuda_bf16.h>
#include <float.h>
#include <math.h>

#define B_   16
#define C_   256
#define H_   128
#define W_   128
#define HW_  (H_ * W_)           // 16384
#define HW4_ (HW_ / 4)           // 4096
#define BHW_ (B_ * HW_)

// Q[kh][b][h][w]: 1-D conv contribution of feat row h with vertical tap kh.
// out[h] = Q0[h-1] + Q1[h] + Q2[h+1].
__device__ float g_Q[3 * BHW_];
// E[side][kh][b*H+rt]: boundary fixes for w=63 (side0) / w=64 (side1).
__device__ float g_E[2 * 3 * B_ * H_];
// Per-output-row contributor counters (target 6 interior / 4 edges).
// Reset to 0 by the last arriver -> graph-replay clean.
__device__ int g_cnt[B_ * H_];

__device__ __forceinline__ float fast_sigmoid(float x)
{
    float y = -x * 1.4426950408889634f;
    y = fminf(fmaxf(y, -126.0f), 126.0f);
    float n = floorf(y);
    float f = y - n;
    float p = 1.3333558146428443e-3f;
    p = fmaf(p, f, 9.8105352697968360e-3f);
    p = fmaf(p, f, 5.5518340325804030e-2f);
    p = fmaf(p, f, 2.4017933341410937e-1f);
    p = fmaf(p, f, 6.9314692312196549e-1f);
    p = fmaf(p, f, 1.0f);
    const float s = __int_as_float(((int)n + 127) << 23);
    const float t = s * p;                   // e^(-x)
    const float u = 1.0f + t;
    float r = __uint_as_float(0x7EF311C3u - __float_as_uint(u));
    r = r * (2.0f - u * r);
    r = r * (2.0f - u * r);
    r = r * (2.0f - u * r);
    return r;
}

// ---------------------------------------------------------------------------
// Single kernel: R6 streaming body + Q/E epilogue + last-arriver out-row
// compute. No waiting anywhere; no second kernel; no global sync.
// ---------------------------------------------------------------------------
__global__ __launch_bounds__(256, 8) void fused_spatial_attention(
    const float* __restrict__ x,
    const float* __restrict__ conv_w,   // [1,2,3,3] OIHW
    float* __restrict__ out)            // [B,1,H,W]
{
    __shared__ float4 s_sum[256];
    __shared__ float4 s_max[256];
    __shared__ float  s_f[2][66];        // padded half-row: [ch][1+64+1]
    __shared__ float  s_w[18];
    __shared__ int    s_todo;            // bitmask of out-rows to compute

    const int tid  = threadIdx.x;
    const int col  = tid & 15;
    const int cs   = tid >> 4;

    const int blk    = blockIdx.x;             // 0..4095
    const int row_id = blk >> 1;
    const int half   = blk & 1;
    const int b      = row_id >> 7;
    const int h      = row_id & 127;
    const int hw4    = (h << 5) + (half << 4) + col;

    if (tid < 18) s_w[tid] = __ldg(conv_w + tid);
    if (tid == 0) s_todo = 0;

    // ---- Streaming reduction (R6 body, byte-identical) -------------------
    const float4* xb = reinterpret_cast<const float4*>(x)
                     + (size_t)b * C_ * HW4_ + (size_t)(cs * 16) * HW4_ + hw4;

    float4 s = make_float4(0.f, 0.f, 0.f, 0.f);
    float4 m = make_float4(-FLT_MAX, -FLT_MAX, -FLT_MAX, -FLT_MAX);

    #pragma unroll
    for (int c = 0; c < 16; ++c) {
        float4 v = __ldcs(xb + (size_t)c * HW4_);
        s.x += v.x; s.y += v.y; s.z += v.z; s.w += v.w;
        m.x = fmaxf(m.x, v.x); m.y = fmaxf(m.y, v.y);
        m.z = fmaxf(m.z, v.z); m.w = fmaxf(m.w, v.w);
    }

    s_sum[tid] = s;
    s_max[tid] = m;
    __syncthreads();

    if (tid < 16) {
        #pragma unroll
        for (int k = 1; k < 16; ++k) {
            float4 ps = s_sum[tid + k * 16];
            float4 pm = s_max[tid + k * 16];
            s.x += ps.x; s.y += ps.y; s.z += ps.z; s.w += ps.w;
            m.x = fmaxf(m.x, pm.x); m.y = fmaxf(m.y, pm.y);
            m.z = fmaxf(m.z, pm.z); m.w = fmaxf(m.w, pm.w);
        }
        const float inv = 1.0f / (float)C_;
        s_f[0][1 + 4 * tid + 0] = s.x * inv;
        s_f[0][1 + 4 * tid + 1] = s.y * inv;
        s_f[0][1 + 4 * tid + 2] = s.z * inv;
        s_f[0][1 + 4 * tid + 3] = s.w * inv;
        s_f[1][1 + 4 * tid + 0] = m.x;
        s_f[1][1 + 4 * tid + 1] = m.y;
        s_f[1][1 + 4 * tid + 2] = m.z;
        s_f[1][1 + 4 * tid + 3] = m.w;
    }
    if (tid >= 16 && tid < 18) {
        s_f[tid - 16][0]  = 0.f;
        s_f[tid - 16][65] = 0.f;
    }
    __syncthreads();

    // ---- Epilogue A: Q row contributions (64 threads, coalesced) ---------
    if (tid < 64) {
        float q0 = 0.f, q1 = 0.f, q2 = 0.f;
        #pragma unroll
        for (int kw = 0; kw < 3; ++kw) {
            const float f0 = s_f[0][tid + kw];
            const float f1 = s_f[1][tid + kw];
            q0 = fmaf(f0, s_w[0 * 3 + kw], fmaf(f1, s_w[9 + 0 * 3 + kw], q0));
            q1 = fmaf(f0, s_w[1 * 3 + kw], fmaf(f1, s_w[9 + 1 * 3 + kw], q1));
            q2 = fmaf(f0, s_w[2 * 3 + kw], fmaf(f1, s_w[9 + 2 * 3 + kw], q2));
        }
        const int base = b * HW_ + h * W_ + (half << 6) + tid;
        g_Q[0 * BHW_ + base] = q0;
        g_Q[1 * BHW_ + base] = q1;
        g_Q[2 * BHW_ + base] = q2;
    }

    // ---- Epilogue B: boundary fix terms ----------------------------------
    if (tid == 64) {
        const int side = 1 - half;
        const int kw   = (side == 0) ? 2 : 0;
        const int eidx = (side == 0) ? 1 : 64;
        const float e0 = s_f[0][eidx];
        const float e1 = s_f[1][eidx];
        #pragma unroll
        for (int kh = 0; kh < 3; ++kh) {
            const int rt = h + 1 - kh;
            if (rt < 0 || rt >= H_) continue;
            g_E[(side * 3 + kh) * B_ * H_ + b * H_ + rt] =
                e0 * s_w[kh * 3 + kw] + e1 * s_w[9 + kh * 3 + kw];
        }
    }

    // ---- Publish, then last-arriver claims ready out-rows ----------------
    __threadfence();       // order this block's Q/E stores device-wide
    __syncthreads();       // all stores issued before the claim

    if (tid == 0) {
        int mask = 0;
        #pragma unroll
        for (int dr = -1; dr <= 1; ++dr) {
            const int rt = h + dr;
            if (rt < 0 || rt >= H_) continue;
            const int tgt = (rt == 0 || rt == H_ - 1) ? 4 : 6;
            const int g   = b * H_ + rt;
            if (atomicAdd(&g_cnt[g], 1) == tgt - 1) {
                mask |= (1 << (dr + 1));
                atomicExch(&g_cnt[g], 0);   // reset for next graph replay
            }
        }
        s_todo = mask;
    }
    __syncthreads();

    const int mask = s_todo;
    if (mask != 0 && tid < 128) {
        __threadfence();   // acquire: order Q/E reads after counter observation
        const int w = tid;
        #pragma unroll
        for (int dr = -1; dr <= 1; ++dr) {
            if (!(mask & (1 << (dr + 1)))) continue;
            const int rt = h + dr;
            const int rowbase = b * HW_ + rt * W_ + w;

            float v = __ldcg(&g_Q[1 * BHW_ + rowbase]);
            if (rt >= 1)      v += __ldcg(&g_Q[0 * BHW_ + rowbase - W_]);
            if (rt <= H_ - 2) v += __ldcg(&g_Q[2 * BHW_ + rowbase + W_]);

            if (w == 63 || w == 64) {
                const int side = (w == 64);
                const int eb   = side * 3 * B_ * H_ + b * H_ + rt;
                v += __ldcg(&g_E[eb + 1 * B_ * H_]);
                if (rt >= 1)      v += __ldcg(&g_E[eb + 0 * B_ * H_]);
                if (rt <= H_ - 2) v += __ldcg(&g_E[eb + 2 * B_ * H_]);
            }

            out[rowbase] = fast_sigmoid(v);
        }
    }
}

// ---------------------------------------------------------------------------
extern "C" void kernel_launch(void* const* d_in, const int* in_sizes, int n_in,
                              void* d_out, int out_size)
{
    const float* x      = (const float*)d_in[0];   // [16,256,128,128] f32
    const float* conv_w = (const float*)d_in[1];   // [1,2,3,3] f32
    float*       out    = (float*)d_out;           // [16,1,128,128] f32

    fused_spatial_attention<<<4096, 256>>>(x, conv_w, out);
}